// round 13
// baseline (speedup 1.0000x reference)
#include <cuda_runtime.h>
#include <math.h>
#include <stdint.h>

#define NN   100000
#define NE   1600000
#define ET   (NE + NN)
#define VISD 512
#define TXTD 768
#define FEATD 131
#define LDA  132
#define HID  128
#define SCAN_B 1024
#define NBLK  ((NN + SCAN_B - 1) / SCAN_B)

// ---------------- scratch ----------------
static __device__ float    g_node[NN * LDA];
static __device__ float    g_h   [NN * HID];
static __device__ float    g_x1  [NN * HID];
static __device__ float    g_agg [NN * HID];
static __device__ float    g_as  [NN];
static __device__ float    g_ad  [NN];
static __device__ float    g_ang [NN * 2];
static __device__ float    g_dis [NN * 2];
static __device__ int      g_cnt [NN];
static __device__ int      g_rowptr[NN + 1];
static __device__ int      g_wofs[NN];
static __device__ int      g_csr [ET];
static __device__ int      g_bsum[128];

// ---------------- helpers ----------------
__device__ __forceinline__ float gelu_exact(float x) {
    return 0.5f * x * (1.0f + erff(x * 0.70710678118654752f));
}
__device__ __forceinline__ unsigned long long pk2(float lo, float hi) {
    unsigned long long r;
    asm("mov.b64 %0, {%1, %2};" : "=l"(r) : "f"(lo), "f"(hi));
    return r;
}
__device__ __forceinline__ void upk2(unsigned long long v, float& lo, float& hi) {
    asm("mov.b64 {%0, %1}, %2;" : "=f"(lo), "=f"(hi) : "l"(v));
}
__device__ __forceinline__ unsigned long long fma2(unsigned long long a, unsigned long long b,
                                                   unsigned long long c) {
    unsigned long long d;
    asm("fma.rn.f32x2 %0, %1, %2, %3;" : "=l"(d) : "l"(a), "l"(b), "l"(c));
    return d;
}

// ---------------- trivial fills ----------------
__global__ void fill_i(int* p, int v, int n) {
    int i = blockIdx.x * blockDim.x + threadIdx.x;
    if (i < n) p[i] = v;
}

// ---------------- CSR build ----------------
__global__ void hist_kernel(const int* __restrict__ edges) {
    int i = blockIdx.x * blockDim.x + threadIdx.x;
    if (i >= ET) return;
    int d = (i < NE) ? edges[2 * i + 1] : (i - NE);
    atomicAdd(&g_cnt[d], 1);
}
__global__ void scan_block() {
    __shared__ int sm[SCAN_B];
    int i = blockIdx.x * SCAN_B + threadIdx.x;
    int v = (i < NN) ? g_cnt[i] : 0;
    sm[threadIdx.x] = v;
    __syncthreads();
    #pragma unroll
    for (int o = 1; o < SCAN_B; o <<= 1) {
        int t = (threadIdx.x >= o) ? sm[threadIdx.x - o] : 0;
        __syncthreads();
        sm[threadIdx.x] += t;
        __syncthreads();
    }
    if (i < NN) g_rowptr[i] = sm[threadIdx.x] - v;
    if (threadIdx.x == SCAN_B - 1) g_bsum[blockIdx.x] = sm[SCAN_B - 1];
}
__global__ void scan_sums() {
    __shared__ int sm[128];
    int v = (threadIdx.x < NBLK) ? g_bsum[threadIdx.x] : 0;
    sm[threadIdx.x] = v;
    __syncthreads();
    #pragma unroll
    for (int o = 1; o < 128; o <<= 1) {
        int t = (threadIdx.x >= o) ? sm[threadIdx.x - o] : 0;
        __syncthreads();
        sm[threadIdx.x] += t;
        __syncthreads();
    }
    if (threadIdx.x < NBLK) g_bsum[threadIdx.x] = sm[threadIdx.x] - v;
}
__global__ void scan_add() {
    int i = blockIdx.x * blockDim.x + threadIdx.x;
    if (i < NN) {
        int v = g_rowptr[i] + g_bsum[i / SCAN_B];
        g_rowptr[i] = v;
        g_wofs[i]   = v;
    }
    if (i == 0) g_rowptr[NN] = ET;
}
__global__ void scatter_csr(const int* __restrict__ edges) {
    int i = blockIdx.x * blockDim.x + threadIdx.x;
    if (i >= ET) return;
    int s, d;
    if (i < NE) { s = edges[2 * i]; d = edges[2 * i + 1]; }
    else        { s = d = i - NE; }
    int pos = atomicAdd(&g_wofs[d], 1);
    g_csr[pos] = s;
}

// ================= fp32x2 packed-FMA GEMM v4 =================
// 256 threads; thread grid 32 rows (rxl = t&31) x 8 col-groups (cx = t>>5).
// cx is WARP-UNIFORM -> all B loads are broadcast (1 wavefront).
// BM = 128 (RPT=4, rows strided by 32), BN = 8*CPT.
template<int CPT, bool GELU>
__global__ void __launch_bounds__(256, 2)
gemm4(const float* __restrict__ A, int lda, int K, int M,
      const float* __restrict__ W, int wld,
      const float* __restrict__ bias,
      const int* __restrict__ sidx,
      float* __restrict__ C, int ldc, int ccol0)
{
    constexpr int RPT = 4;
    constexpr int BM  = 128;
    constexpr int BN  = 8 * CPT;
    constexpr int PPT = CPT / 2;

    __shared__ __align__(16) float As[16][BM];
    __shared__ __align__(16) float Bs[16][BN];
    __shared__ float biasS[BN];

    const int t   = threadIdx.x;
    const int rxl = t & 31;
    const int cx  = t >> 5;          // warp-uniform
    const int r0  = blockIdx.x * BM;

    if (t < BN) biasS[t] = bias ? bias[t] : 0.f;

    unsigned long long acc[RPT][PPT];
    #pragma unroll
    for (int i = 0; i < RPT; i++)
        #pragma unroll
        for (int p = 0; p < PPT; p++) acc[i][p] = 0ull;

    for (int k0 = 0; k0 < K; k0 += 16) {
        // ---- stage A: 128 rows x 16 k, transposed into As[k][row] ----
        #pragma unroll
        for (int it = 0; it < 2; it++) {
            int id  = t + 256 * it;
            int row = id >> 2;
            int kq  = (id & 3) * 4;
            int gr = r0 + row, gk = k0 + kq;
            float4 v = make_float4(0.f, 0.f, 0.f, 0.f);
            if (gr < M) {
                const float* ap = &A[(size_t)gr * lda + gk];
                if (gk + 4 <= K) v = *reinterpret_cast<const float4*>(ap);
                else {
                    if (gk + 0 < K) v.x = ap[0];
                    if (gk + 1 < K) v.y = ap[1];
                    if (gk + 2 < K) v.z = ap[2];
                }
            }
            As[kq + 0][row] = v.x;
            As[kq + 1][row] = v.y;
            As[kq + 2][row] = v.z;
            As[kq + 3][row] = v.w;
        }
        // ---- stage B: 16 k x BN cols ----
        #pragma unroll
        for (int it = 0; it < BN / 64; it++) {
            int id = t + 256 * it;
            int kk = id / (BN / 4);
            int n4 = (id % (BN / 4)) * 4;
            int gk = k0 + kk;
            float4 v = make_float4(0.f, 0.f, 0.f, 0.f);
            if (gk < K) v = *reinterpret_cast<const float4*>(&W[(size_t)gk * wld + n4]);
            *reinterpret_cast<float4*>(&Bs[kk][n4]) = v;
        }
        __syncthreads();

        #pragma unroll 4
        for (int k = 0; k < 16; k++) {
            unsigned long long ap[RPT];
            #pragma unroll
            for (int i = 0; i < RPT; i++) {
                float a = As[k][rxl + 32 * i];
                ap[i] = pk2(a, a);
            }
            unsigned long long bv[PPT];
            #pragma unroll
            for (int j = 0; j < CPT / 4; j++) {
                ulonglong2 q = *reinterpret_cast<const ulonglong2*>(&Bs[k][cx * CPT + 4 * j]);
                bv[2 * j]     = q.x;
                bv[2 * j + 1] = q.y;
            }
            #pragma unroll
            for (int i = 0; i < RPT; i++)
                #pragma unroll
                for (int p = 0; p < PPT; p++)
                    acc[i][p] = fma2(ap[i], bv[p], acc[i][p]);
        }
        __syncthreads();
    }

    // ---- epilogue ----
    #pragma unroll
    for (int i = 0; i < RPT; i++) {
        int r = r0 + rxl + 32 * i;
        if (r >= M) continue;
        int orow = sidx ? sidx[r] : r;
        float f[CPT];
        #pragma unroll
        for (int p = 0; p < PPT; p++) upk2(acc[i][p], f[2 * p], f[2 * p + 1]);
        #pragma unroll
        for (int e = 0; e < CPT; e++) {
            float v = f[e] + biasS[cx * CPT + e];
            if (GELU) v = gelu_exact(v);
            f[e] = v;
        }
        float* cp = &C[(size_t)orow * ldc + ccol0 + cx * CPT];
        #pragma unroll
        for (int q = 0; q < CPT / 4; q++)
            *reinterpret_cast<float4*>(cp + 4 * q) =
                make_float4(f[4 * q], f[4 * q + 1], f[4 * q + 2], f[4 * q + 3]);
    }
}

// ---------------- ars -> node cols 128..130 ----------------
__global__ void ars_scatter(const float* __restrict__ ars, const int* __restrict__ ci) {
    int i = blockIdx.x * blockDim.x + threadIdx.x;
    if (i >= NN) return;
    int dst = ci[i];
    g_node[(size_t)dst * LDA + 128] = gelu_exact(ars[3 * i + 0]);
    g_node[(size_t)dst * LDA + 129] = gelu_exact(ars[3 * i + 1]);
    g_node[(size_t)dst * LDA + 130] = gelu_exact(ars[3 * i + 2]);
}

// ---------------- per-node attention scores ----------------
__global__ void attn_scores(const float* __restrict__ ws, const float* __restrict__ wd) {
    int gw   = (blockIdx.x * blockDim.x + threadIdx.x) >> 5;
    int lane = threadIdx.x & 31;
    if (gw >= NN) return;
    float4 hv = *reinterpret_cast<const float4*>(&g_h[(size_t)gw * HID + lane * 4]);
    float4 a  = *reinterpret_cast<const float4*>(&ws[lane * 4]);
    float4 b  = *reinterpret_cast<const float4*>(&wd[lane * 4]);
    float s = hv.x * a.x + hv.y * a.y + hv.z * a.z + hv.w * a.w;
    float d = hv.x * b.x + hv.y * b.y + hv.z * b.z + hv.w * b.w;
    #pragma unroll
    for (int o = 16; o; o >>= 1) {
        s += __shfl_xor_sync(0xffffffffu, s, o);
        d += __shfl_xor_sync(0xffffffffu, d, o);
    }
    if (lane == 0) { g_as[gw] = s; g_ad[gw] = d; }
}

// ---------------- pull-based GAT aggregation ----------------
__global__ void gat_pull(const float* __restrict__ bias, int do_relu,
                         float* __restrict__ out)
{
    int w    = (blockIdx.x * blockDim.x + threadIdx.x) >> 5;
    int lane = threadIdx.x & 31;
    if (w >= NN) return;
    const int start = g_rowptr[w];
    const int end   = g_rowptr[w + 1];
    const float adw = g_ad[w];

    float m = -1e30f, ssum = 0.f;
    for (int i = start + lane; i < end; i += 32) {
        float e = g_as[g_csr[i]] + adw;
        e = (e > 0.f) ? e : 0.2f * e;
        if (e > m) { ssum = ssum * expf(m - e) + 1.0f; m = e; }
        else       { ssum += expf(e - m); }
    }
    #pragma unroll
    for (int o = 16; o; o >>= 1) {
        float mo = __shfl_xor_sync(0xffffffffu, m, o);
        float so = __shfl_xor_sync(0xffffffffu, ssum, o);
        float mn = fmaxf(m, mo);
        ssum = ssum * expf(m - mn) + so * expf(mo - mn);
        m = mn;
    }
    const float inv = 1.0f / (ssum + 1e-16f);

    float4 acc = make_float4(0.f, 0.f, 0.f, 0.f);
    const float4* hb = reinterpret_cast<const float4*>(g_h);
    for (int i = start; i < end; i++) {
        int src = g_csr[i];
        float e = g_as[src] + adw;
        e = (e > 0.f) ? e : 0.2f * e;
        float alpha = expf(e - m) * inv;
        float4 hv = hb[(size_t)src * 32 + lane];
        acc.x = fmaf(alpha, hv.x, acc.x);
        acc.y = fmaf(alpha, hv.y, acc.y);
        acc.z = fmaf(alpha, hv.z, acc.z);
        acc.w = fmaf(alpha, hv.w, acc.w);
    }
    if (bias) {
        float4 bb = *reinterpret_cast<const float4*>(&bias[lane * 4]);
        acc.x += bb.x; acc.y += bb.y; acc.z += bb.z; acc.w += bb.w;
    }
    if (do_relu) {
        acc.x = fmaxf(acc.x, 0.f); acc.y = fmaxf(acc.y, 0.f);
        acc.z = fmaxf(acc.z, 0.f); acc.w = fmaxf(acc.w, 0.f);
    }
    *reinterpret_cast<float4*>(&out[(size_t)w * HID + lane * 4]) = acc;
}

// ---------------- final per-node ----------------
__global__ void final_node(const float* __restrict__ b1,
                           const float* __restrict__ Wa, const float* __restrict__ ba,
                           const float* __restrict__ Wd, const float* __restrict__ bd,
                           float* __restrict__ out)
{
    int gw   = (blockIdx.x * blockDim.x + threadIdx.x) >> 5;
    int lane = threadIdx.x & 31;
    if (gw >= NN) return;
    float4 g;
    {
        float4 v = *reinterpret_cast<const float4*>(&g_agg[(size_t)gw * HID + lane * 4]);
        float4 bb = *reinterpret_cast<const float4*>(&b1[lane * 4]);
        g.x = gelu_exact(v.x + bb.x);
        g.y = gelu_exact(v.y + bb.y);
        g.z = gelu_exact(v.z + bb.z);
        g.w = gelu_exact(v.w + bb.w);
    }
    *reinterpret_cast<float4*>(&out[(size_t)gw * HID + lane * 4]) = g;
    int k = lane * 4;
    float a0 = g.x * Wa[2 * k]     + g.y * Wa[2 * (k + 1)]     + g.z * Wa[2 * (k + 2)]     + g.w * Wa[2 * (k + 3)];
    float a1 = g.x * Wa[2 * k + 1] + g.y * Wa[2 * (k + 1) + 1] + g.z * Wa[2 * (k + 2) + 1] + g.w * Wa[2 * (k + 3) + 1];
    float d0 = g.x * Wd[2 * k]     + g.y * Wd[2 * (k + 1)]     + g.z * Wd[2 * (k + 2)]     + g.w * Wd[2 * (k + 3)];
    float d1 = g.x * Wd[2 * k + 1] + g.y * Wd[2 * (k + 1) + 1] + g.z * Wd[2 * (k + 2) + 1] + g.w * Wd[2 * (k + 3) + 1];
    #pragma unroll
    for (int o = 16; o; o >>= 1) {
        a0 += __shfl_xor_sync(0xffffffffu, a0, o);
        a1 += __shfl_xor_sync(0xffffffffu, a1, o);
        d0 += __shfl_xor_sync(0xffffffffu, d0, o);
        d1 += __shfl_xor_sync(0xffffffffu, d1, o);
    }
    if (lane == 0) {
        g_ang[2 * gw]     = a0 + ba[0];
        g_ang[2 * gw + 1] = a1 + ba[1];
        g_dis[2 * gw]     = d0 + bd[0];
        g_dis[2 * gw + 1] = d1 + bd[1];
    }
}

// ---------------- edge prediction ----------------
__global__ void pred_kernel(const int* __restrict__ edges, float* __restrict__ pred) {
    int i = blockIdx.x * blockDim.x + threadIdx.x;
    if (i >= NE) return;
    int s = edges[2 * i], d = edges[2 * i + 1];
    float ap = g_ang[2 * s] * g_ang[2 * d] + g_ang[2 * s + 1] * g_ang[2 * d + 1];
    float dp = g_dis[2 * s] * g_dis[2 * d] + g_dis[2 * s + 1] * g_dis[2 * d + 1];
    pred[2 * i]     = ap;
    pred[2 * i + 1] = dp;
}

// ---------------- launch ----------------
extern "C" void kernel_launch(void* const* d_in, const int* in_sizes, int n_in,
                              void* d_out, int out_size)
{
    const float* img  = (const float*)d_in[0];
    const float* txt  = (const float*)d_in[1];
    const int*   ci   = (const int*)  d_in[2];
    const int*   edges= (const int*)  d_in[4];
    const float* ars  = (const float*)d_in[5];
    const float* Wi   = (const float*)d_in[6];
    const float* bi   = (const float*)d_in[7];
    const float* Wt   = (const float*)d_in[8];
    const float* bt   = (const float*)d_in[9];
    const float* W0   = (const float*)d_in[10];
    const float* as0  = (const float*)d_in[11];
    const float* ad0  = (const float*)d_in[12];
    const float* b0   = (const float*)d_in[13];
    const float* W1   = (const float*)d_in[14];
    const float* as1  = (const float*)d_in[15];
    const float* ad1  = (const float*)d_in[16];
    const float* b1   = (const float*)d_in[17];
    const float* Wa   = (const float*)d_in[18];
    const float* ba   = (const float*)d_in[19];
    const float* Wd   = (const float*)d_in[20];
    const float* bd   = (const float*)d_in[21];
    float* out  = (float*)d_out;
    float* pred = (float*)d_out + (size_t)NN * HID;

    float *p_node, *p_h, *p_x1, *p_agg;
    int *p_cnt;
    cudaGetSymbolAddress((void**)&p_node, g_node);
    cudaGetSymbolAddress((void**)&p_h,    g_h);
    cudaGetSymbolAddress((void**)&p_x1,   g_x1);
    cudaGetSymbolAddress((void**)&p_agg,  g_agg);
    cudaGetSymbolAddress((void**)&p_cnt,  g_cnt);

    const int T = 256;
    const int GB = (NN + 127) / 128;          // BM=128 for all GEMMs
    const int node_wblocks = ((NN * 32) + T - 1) / T;
    const int edge_blocks  = (ET + T - 1) / T;

    // launches 1-3
    fill_i<<<(NN + T - 1) / T, T>>>(p_cnt, 0, NN);
    hist_kernel<<<edge_blocks, T>>>(edges);
    scan_block<<<NBLK, SCAN_B>>>();
    // launch 4 — big projection GEMM (ncu capture slot)
    gemm4<8, true><<<GB, 256>>>(txt, TXTD, TXTD, NN, Wt, 64, bt, ci, p_node, LDA, 64);
    // rest of CSR build
    scan_sums<<<1, 128>>>();
    scan_add<<<(NN + T - 1) / T, T>>>();
    scatter_csr<<<edge_blocks, T>>>(edges);
    // remaining projections (content_indices covers every row -> no fill needed)
    gemm4<8, true><<<GB, 256>>>(img, VISD, VISD, NN, Wi, 64, bi, ci, p_node, LDA, 0);
    ars_scatter<<<(NN + T - 1) / T, T>>>(ars, ci);

    // GAT layer 0 (full 128 columns, one launch)
    gemm4<16, false><<<GB, 256>>>(p_node, LDA, FEATD, NN, W0, HID, nullptr, nullptr, p_h, HID, 0);
    attn_scores<<<node_wblocks, T>>>(as0, ad0);
    gat_pull<<<node_wblocks, T>>>(b0, 1, p_x1);

    // GAT layer 1
    gemm4<16, false><<<GB, 256>>>(p_x1, HID, HID, NN, W1, HID, nullptr, nullptr, p_h, HID, 0);
    attn_scores<<<node_wblocks, T>>>(as1, ad1);
    gat_pull<<<node_wblocks, T>>>(nullptr, 0, p_agg);

    // outputs
    final_node<<<node_wblocks, T>>>(b1, Wa, ba, Wd, bd, out);
    pred_kernel<<<(NE + T - 1) / T, T>>>(edges, pred);
}

// round 15
// speedup vs baseline: 1.4669x; 1.4669x over previous
#include <cuda_runtime.h>
#include <cuda_fp16.h>
#include <math.h>
#include <stdint.h>

#define NN   100000
#define NE   1600000
#define ET   (NE + NN)
#define VISD 512
#define TXTD 768
#define FEATD 131
#define LDA  132
#define HID  128
#define SCAN_B 1024
#define NBLK  ((NN + SCAN_B - 1) / SCAN_B)

// ---------------- scratch ----------------
static __device__ float    g_node[NN * LDA];
static __device__ float    g_h   [NN * HID];
static __device__ float    g_x1  [NN * HID];
static __device__ float    g_agg [NN * HID];
static __device__ float    g_as  [NN];
static __device__ float    g_ad  [NN];
static __device__ float    g_ang [NN * 2];
static __device__ float    g_dis [NN * 2];
static __device__ int      g_cnt [NN];
static __device__ int      g_rowptr[NN + 1];
static __device__ int      g_wofs[NN];
static __device__ int      g_csr [ET];
static __device__ int      g_bsum[128];

// ---------------- helpers ----------------
__device__ __forceinline__ float gelu_exact(float x) {
    return 0.5f * x * (1.0f + erff(x * 0.70710678118654752f));
}
__device__ __forceinline__ uint32_t smem_u32(const void* p) {
    uint32_t a;
    asm("{ .reg .u64 t; cvta.to.shared.u64 t, %1; cvt.u32.u64 %0, t; }" : "=r"(a) : "l"(p));
    return a;
}
__device__ __forceinline__ void ldsm_x4(uint32_t& r0, uint32_t& r1, uint32_t& r2, uint32_t& r3, uint32_t addr) {
    asm volatile("ldmatrix.sync.aligned.m8n8.x4.shared.b16 {%0,%1,%2,%3}, [%4];"
                 : "=r"(r0), "=r"(r1), "=r"(r2), "=r"(r3) : "r"(addr));
}
__device__ __forceinline__ void ldsm_x2(uint32_t& r0, uint32_t& r1, uint32_t addr) {
    asm volatile("ldmatrix.sync.aligned.m8n8.x2.shared.b16 {%0,%1}, [%2];"
                 : "=r"(r0), "=r"(r1) : "r"(addr));
}
__device__ __forceinline__ void mma16816(float* c, uint32_t a0, uint32_t a1, uint32_t a2, uint32_t a3,
                                         uint32_t b0, uint32_t b1) {
    asm volatile("mma.sync.aligned.m16n8k16.row.col.f32.f16.f16.f32 "
                 "{%0,%1,%2,%3}, {%4,%5,%6,%7}, {%8,%9}, {%0,%1,%2,%3};"
                 : "+f"(c[0]), "+f"(c[1]), "+f"(c[2]), "+f"(c[3])
                 : "r"(a0), "r"(a1), "r"(a2), "r"(a3), "r"(b0), "r"(b1));
}

// ---------------- trivial fills ----------------
__global__ void fill_i(int* p, int v, int n) {
    int i = blockIdx.x * blockDim.x + threadIdx.x;
    if (i < n) p[i] = v;
}

// ---------------- CSR build ----------------
__global__ void hist_kernel(const int* __restrict__ edges) {
    int i = blockIdx.x * blockDim.x + threadIdx.x;
    if (i >= ET) return;
    int d = (i < NE) ? edges[2 * i + 1] : (i - NE);
    atomicAdd(&g_cnt[d], 1);
}
__global__ void scan_block() {
    __shared__ int sm[SCAN_B];
    int i = blockIdx.x * SCAN_B + threadIdx.x;
    int v = (i < NN) ? g_cnt[i] : 0;
    sm[threadIdx.x] = v;
    __syncthreads();
    #pragma unroll
    for (int o = 1; o < SCAN_B; o <<= 1) {
        int t = (threadIdx.x >= o) ? sm[threadIdx.x - o] : 0;
        __syncthreads();
        sm[threadIdx.x] += t;
        __syncthreads();
    }
    if (i < NN) g_rowptr[i] = sm[threadIdx.x] - v;
    if (threadIdx.x == SCAN_B - 1) g_bsum[blockIdx.x] = sm[SCAN_B - 1];
}
__global__ void scan_sums() {
    __shared__ int sm[128];
    int v = (threadIdx.x < NBLK) ? g_bsum[threadIdx.x] : 0;
    sm[threadIdx.x] = v;
    __syncthreads();
    #pragma unroll
    for (int o = 1; o < 128; o <<= 1) {
        int t = (threadIdx.x >= o) ? sm[threadIdx.x - o] : 0;
        __syncthreads();
        sm[threadIdx.x] += t;
        __syncthreads();
    }
    if (threadIdx.x < NBLK) g_bsum[threadIdx.x] = sm[threadIdx.x] - v;
}
__global__ void scan_add() {
    int i = blockIdx.x * blockDim.x + threadIdx.x;
    if (i < NN) {
        int v = g_rowptr[i] + g_bsum[i / SCAN_B];
        g_rowptr[i] = v;
        g_wofs[i]   = v;
    }
    if (i == 0) g_rowptr[NN] = ET;
}
__global__ void scatter_csr(const int* __restrict__ edges) {
    int i = blockIdx.x * blockDim.x + threadIdx.x;
    if (i >= ET) return;
    int s, d;
    if (i < NE) { s = edges[2 * i]; d = edges[2 * i + 1]; }
    else        { s = d = i - NE; }
    int pos = atomicAdd(&g_wofs[d], 1);
    g_csr[pos] = s;
}

// ================= fp16 mma.sync GEMM (single MMA per tile) =================
// C = A[M,K] @ W[K,BN] (+bias, +gelu, optional row scatter via sidx)
// fp16 inputs (rn-converted during staging), fp32 accumulate.
#define BM 128
#define BK 32
#define SPD 40   // padded smem stride in halfs

template<int BN, bool GELU>
__global__ void __launch_bounds__(256)
gemm_h(const float* __restrict__ A, int lda, int K, int M,
       const float* __restrict__ W,
       const float* __restrict__ bias,
       const int* __restrict__ sidx,
       float* __restrict__ C, int ldc, int ccol0)
{
    constexpr int WARPS_M = (BN == 64) ? 4 : 2;
    constexpr int WM = BM / WARPS_M;          // 32 or 64
    constexpr int MT = WM / 16;               // 2 or 4
    constexpr int NT = 4;                     // WN = 32

    __shared__ __align__(16) uint16_t Ah[BM][SPD];
    __shared__ __align__(16) uint16_t Bh[BN][SPD];

    const int t = threadIdx.x, lane = t & 31, wid = t >> 5;
    const int wm0 = (wid % WARPS_M) * WM;
    const int wn0 = (wid / WARPS_M) * 32;
    const int r0  = blockIdx.x * BM;
    const uint32_t sAh = smem_u32(Ah);
    const uint32_t sBh = smem_u32(Bh);

    float acc[MT][NT][4];
    #pragma unroll
    for (int i = 0; i < MT; i++)
        #pragma unroll
        for (int j = 0; j < NT; j++)
            #pragma unroll
            for (int e = 0; e < 4; e++) acc[i][j][e] = 0.f;

    const int nch = (K + BK - 1) / BK;
    for (int c = 0; c < nch; c++) {
        const int k0 = c * BK;
        // ---- stage A (BM x BK) as fp16 ----
        #pragma unroll
        for (int it = 0; it < 4; it++) {
            int id = t + 256 * it;
            int row = id >> 3;
            int kq  = (id & 7) * 4;
            int gr = r0 + row, gk = k0 + kq;
            float4 v = make_float4(0.f, 0.f, 0.f, 0.f);
            if (gr < M) {
                const float* ap = &A[(size_t)gr * lda + gk];
                if (gk + 4 <= K) v = *reinterpret_cast<const float4*>(ap);
                else {
                    if (gk + 0 < K) v.x = ap[0];
                    if (gk + 1 < K) v.y = ap[1];
                    if (gk + 2 < K) v.z = ap[2];
                }
            }
            uint16_t h0 = __half_as_ushort(__float2half_rn(v.x));
            uint16_t h1 = __half_as_ushort(__float2half_rn(v.y));
            uint16_t h2 = __half_as_ushort(__float2half_rn(v.z));
            uint16_t h3 = __half_as_ushort(__float2half_rn(v.w));
            *reinterpret_cast<uint2*>(&Ah[row][kq]) = make_uint2(
                (uint32_t)h0 | ((uint32_t)h1 << 16), (uint32_t)h2 | ((uint32_t)h3 << 16));
        }
        // ---- stage B (BN x BK) from W[K, BN] (transposed into [n][k]) ----
        #pragma unroll
        for (int it = 0; it < BK * (BN / 4) / 256; it++) {
            int id = t + 256 * it;
            int kk = id / (BN / 4);
            int n4 = (id % (BN / 4)) * 4;
            int gk = k0 + kk;
            float4 v = make_float4(0.f, 0.f, 0.f, 0.f);
            if (gk < K) v = *reinterpret_cast<const float4*>(&W[(size_t)gk * BN + n4]);
            Bh[n4 + 0][kk] = __half_as_ushort(__float2half_rn(v.x));
            Bh[n4 + 1][kk] = __half_as_ushort(__float2half_rn(v.y));
            Bh[n4 + 2][kk] = __half_as_ushort(__float2half_rn(v.z));
            Bh[n4 + 3][kk] = __half_as_ushort(__float2half_rn(v.w));
        }
        __syncthreads();

        // ---- MMA: 2 k16 steps ----
        #pragma unroll
        for (int ks = 0; ks < 2; ks++) {
            const int l16 = lane & 15, lk8 = (lane >> 4) * 8;
            uint32_t a[MT][4];
            #pragma unroll
            for (int mt = 0; mt < MT; mt++) {
                uint32_t off = (uint32_t)((wm0 + mt * 16 + l16) * SPD + ks * 16 + lk8) * 2;
                ldsm_x4(a[mt][0], a[mt][1], a[mt][2], a[mt][3], sAh + off);
            }
            uint32_t b[NT][2];
            #pragma unroll
            for (int nt = 0; nt < NT; nt++) {
                uint32_t off = (uint32_t)((wn0 + nt * 8 + (l16 & 7)) * SPD + ks * 16 + (l16 >> 3) * 8) * 2;
                ldsm_x2(b[nt][0], b[nt][1], sBh + off);
            }
            #pragma unroll
            for (int mt = 0; mt < MT; mt++)
                #pragma unroll
                for (int nt = 0; nt < NT; nt++)
                    mma16816(acc[mt][nt], a[mt][0], a[mt][1], a[mt][2], a[mt][3], b[nt][0], b[nt][1]);
        }
        __syncthreads();
    }

    // ---- epilogue ----
    const int gp = lane >> 2, q2 = (lane & 3) * 2;
    #pragma unroll
    for (int mt = 0; mt < MT; mt++) {
        int r1 = r0 + wm0 + mt * 16 + gp;
        int r2 = r1 + 8;
        int o1 = 0, o2 = 0;
        bool v1 = (r1 < M), v2 = (r2 < M);
        if (v1) o1 = sidx ? sidx[r1] : r1;
        if (v2) o2 = sidx ? sidx[r2] : r2;
        #pragma unroll
        for (int nt = 0; nt < NT; nt++) {
            int col = wn0 + nt * 8 + q2;
            float b0 = bias ? bias[col]     : 0.f;
            float b1 = bias ? bias[col + 1] : 0.f;
            float2 u, w;
            u.x = acc[mt][nt][0] + b0; u.y = acc[mt][nt][1] + b1;
            w.x = acc[mt][nt][2] + b0; w.y = acc[mt][nt][3] + b1;
            if (GELU) {
                u.x = gelu_exact(u.x); u.y = gelu_exact(u.y);
                w.x = gelu_exact(w.x); w.y = gelu_exact(w.y);
            }
            if (v1) *reinterpret_cast<float2*>(&C[(size_t)o1 * ldc + ccol0 + col]) = u;
            if (v2) *reinterpret_cast<float2*>(&C[(size_t)o2 * ldc + ccol0 + col]) = w;
        }
    }
}

// ---------------- ars -> node cols 128..130 ----------------
__global__ void ars_scatter(const float* __restrict__ ars, const int* __restrict__ ci) {
    int i = blockIdx.x * blockDim.x + threadIdx.x;
    if (i >= NN) return;
    int dst = ci[i];
    g_node[(size_t)dst * LDA + 128] = gelu_exact(ars[3 * i + 0]);
    g_node[(size_t)dst * LDA + 129] = gelu_exact(ars[3 * i + 1]);
    g_node[(size_t)dst * LDA + 130] = gelu_exact(ars[3 * i + 2]);
}

// ---------------- per-node attention scores ----------------
__global__ void attn_scores(const float* __restrict__ ws, const float* __restrict__ wd) {
    int gw   = (blockIdx.x * blockDim.x + threadIdx.x) >> 5;
    int lane = threadIdx.x & 31;
    if (gw >= NN) return;
    float4 hv = *reinterpret_cast<const float4*>(&g_h[(size_t)gw * HID + lane * 4]);
    float4 a  = *reinterpret_cast<const float4*>(&ws[lane * 4]);
    float4 b  = *reinterpret_cast<const float4*>(&wd[lane * 4]);
    float s = hv.x * a.x + hv.y * a.y + hv.z * a.z + hv.w * a.w;
    float d = hv.x * b.x + hv.y * b.y + hv.z * b.z + hv.w * b.w;
    #pragma unroll
    for (int o = 16; o; o >>= 1) {
        s += __shfl_xor_sync(0xffffffffu, s, o);
        d += __shfl_xor_sync(0xffffffffu, d, o);
    }
    if (lane == 0) { g_as[gw] = s; g_ad[gw] = d; }
}

// ---------------- pull-based GAT aggregation ----------------
__global__ void gat_pull(const float* __restrict__ bias, int do_relu,
                         float* __restrict__ out)
{
    int w    = (blockIdx.x * blockDim.x + threadIdx.x) >> 5;
    int lane = threadIdx.x & 31;
    if (w >= NN) return;
    const int start = g_rowptr[w];
    const int end   = g_rowptr[w + 1];
    const float adw = g_ad[w];

    float m = -1e30f, ssum = 0.f;
    for (int i = start + lane; i < end; i += 32) {
        float e = g_as[g_csr[i]] + adw;
        e = (e > 0.f) ? e : 0.2f * e;
        if (e > m) { ssum = ssum * expf(m - e) + 1.0f; m = e; }
        else       { ssum += expf(e - m); }
    }
    #pragma unroll
    for (int o = 16; o; o >>= 1) {
        float mo = __shfl_xor_sync(0xffffffffu, m, o);
        float so = __shfl_xor_sync(0xffffffffu, ssum, o);
        float mn = fmaxf(m, mo);
        ssum = ssum * expf(m - mn) + so * expf(mo - mn);
        m = mn;
    }
    const float inv = 1.0f / (ssum + 1e-16f);

    float4 acc = make_float4(0.f, 0.f, 0.f, 0.f);
    const float4* hb = reinterpret_cast<const float4*>(g_h);
    for (int i = start; i < end; i++) {
        int src = g_csr[i];
        float e = g_as[src] + adw;
        e = (e > 0.f) ? e : 0.2f * e;
        float alpha = expf(e - m) * inv;
        float4 hv = hb[(size_t)src * 32 + lane];
        acc.x = fmaf(alpha, hv.x, acc.x);
        acc.y = fmaf(alpha, hv.y, acc.y);
        acc.z = fmaf(alpha, hv.z, acc.z);
        acc.w = fmaf(alpha, hv.w, acc.w);
    }
    if (bias) {
        float4 bb = *reinterpret_cast<const float4*>(&bias[lane * 4]);
        acc.x += bb.x; acc.y += bb.y; acc.z += bb.z; acc.w += bb.w;
    }
    if (do_relu) {
        acc.x = fmaxf(acc.x, 0.f); acc.y = fmaxf(acc.y, 0.f);
        acc.z = fmaxf(acc.z, 0.f); acc.w = fmaxf(acc.w, 0.f);
    }
    *reinterpret_cast<float4*>(&out[(size_t)w * HID + lane * 4]) = acc;
}

// ---------------- final per-node ----------------
__global__ void final_node(const float* __restrict__ b1,
                           const float* __restrict__ Wa, const float* __restrict__ ba,
                           const float* __restrict__ Wd, const float* __restrict__ bd,
                           float* __restrict__ out)
{
    int gw   = (blockIdx.x * blockDim.x + threadIdx.x) >> 5;
    int lane = threadIdx.x & 31;
    if (gw >= NN) return;
    float4 g;
    {
        float4 v = *reinterpret_cast<const float4*>(&g_agg[(size_t)gw * HID + lane * 4]);
        float4 bb = *reinterpret_cast<const float4*>(&b1[lane * 4]);
        g.x = gelu_exact(v.x + bb.x);
        g.y = gelu_exact(v.y + bb.y);
        g.z = gelu_exact(v.z + bb.z);
        g.w = gelu_exact(v.w + bb.w);
    }
    *reinterpret_cast<float4*>(&out[(size_t)gw * HID + lane * 4]) = g;
    int k = lane * 4;
    float a0 = g.x * Wa[2 * k]     + g.y * Wa[2 * (k + 1)]     + g.z * Wa[2 * (k + 2)]     + g.w * Wa[2 * (k + 3)];
    float a1 = g.x * Wa[2 * k + 1] + g.y * Wa[2 * (k + 1) + 1] + g.z * Wa[2 * (k + 2) + 1] + g.w * Wa[2 * (k + 3) + 1];
    float d0 = g.x * Wd[2 * k]     + g.y * Wd[2 * (k + 1)]     + g.z * Wd[2 * (k + 2)]     + g.w * Wd[2 * (k + 3)];
    float d1 = g.x * Wd[2 * k + 1] + g.y * Wd[2 * (k + 1) + 1] + g.z * Wd[2 * (k + 2) + 1] + g.w * Wd[2 * (k + 3) + 1];
    #pragma unroll
    for (int o = 16; o; o >>= 1) {
        a0 += __shfl_xor_sync(0xffffffffu, a0, o);
        a1 += __shfl_xor_sync(0xffffffffu, a1, o);
        d0 += __shfl_xor_sync(0xffffffffu, d0, o);
        d1 += __shfl_xor_sync(0xffffffffu, d1, o);
    }
    if (lane == 0) {
        g_ang[2 * gw]     = a0 + ba[0];
        g_ang[2 * gw + 1] = a1 + ba[1];
        g_dis[2 * gw]     = d0 + bd[0];
        g_dis[2 * gw + 1] = d1 + bd[1];
    }
}

// ---------------- edge prediction ----------------
__global__ void pred_kernel(const int* __restrict__ edges, float* __restrict__ pred) {
    int i = blockIdx.x * blockDim.x + threadIdx.x;
    if (i >= NE) return;
    int s = edges[2 * i], d = edges[2 * i + 1];
    float ap = g_ang[2 * s] * g_ang[2 * d] + g_ang[2 * s + 1] * g_ang[2 * d + 1];
    float dp = g_dis[2 * s] * g_dis[2 * d] + g_dis[2 * s + 1] * g_dis[2 * d + 1];
    pred[2 * i]     = ap;
    pred[2 * i + 1] = dp;
}

// ---------------- launch ----------------
extern "C" void kernel_launch(void* const* d_in, const int* in_sizes, int n_in,
                              void* d_out, int out_size)
{
    const float* img  = (const float*)d_in[0];
    const float* txt  = (const float*)d_in[1];
    const int*   ci   = (const int*)  d_in[2];
    const int*   edges= (const int*)  d_in[4];
    const float* ars  = (const float*)d_in[5];
    const float* Wi   = (const float*)d_in[6];
    const float* bi   = (const float*)d_in[7];
    const float* Wt   = (const float*)d_in[8];
    const float* bt   = (const float*)d_in[9];
    const float* W0   = (const float*)d_in[10];
    const float* as0  = (const float*)d_in[11];
    const float* ad0  = (const float*)d_in[12];
    const float* b0   = (const float*)d_in[13];
    const float* W1   = (const float*)d_in[14];
    const float* as1  = (const float*)d_in[15];
    const float* ad1  = (const float*)d_in[16];
    const float* b1   = (const float*)d_in[17];
    const float* Wa   = (const float*)d_in[18];
    const float* ba   = (const float*)d_in[19];
    const float* Wd   = (const float*)d_in[20];
    const float* bd   = (const float*)d_in[21];
    float* out  = (float*)d_out;
    float* pred = (float*)d_out + (size_t)NN * HID;

    float *p_node, *p_h, *p_x1, *p_agg;
    int *p_cnt;
    cudaGetSymbolAddress((void**)&p_node, g_node);
    cudaGetSymbolAddress((void**)&p_h,    g_h);
    cudaGetSymbolAddress((void**)&p_x1,   g_x1);
    cudaGetSymbolAddress((void**)&p_agg,  g_agg);
    cudaGetSymbolAddress((void**)&p_cnt,  g_cnt);

    const int T = 256;
    const int GB = (NN + BM - 1) / BM;
    const int node_wblocks = ((NN * 32) + T - 1) / T;
    const int edge_blocks  = (ET + T - 1) / T;

    // launches 1-3
    fill_i<<<(NN + T - 1) / T, T>>>(p_cnt, 0, NN);
    hist_kernel<<<edge_blocks, T>>>(edges);
    scan_block<<<NBLK, SCAN_B>>>();
    // launch 4 — big projection GEMM (ncu capture slot)
    gemm_h<64, true><<<GB, 256>>>(txt, TXTD, TXTD, NN, Wt, bt, ci, p_node, LDA, 64);
    // rest of CSR build
    scan_sums<<<1, 128>>>();
    scan_add<<<(NN + T - 1) / T, T>>>();
    scatter_csr<<<edge_blocks, T>>>(edges);
    // remaining projections (content_indices covers every row -> no fill needed)
    gemm_h<64, true><<<GB, 256>>>(img, VISD, VISD, NN, Wi, bi, ci, p_node, LDA, 0);
    ars_scatter<<<(NN + T - 1) / T, T>>>(ars, ci);

    // GAT layer 0
    gemm_h<128, false><<<GB, 256>>>(p_node, LDA, FEATD, NN, W0, nullptr, nullptr, p_h, HID, 0);
    attn_scores<<<node_wblocks, T>>>(as0, ad0);
    gat_pull<<<node_wblocks, T>>>(b0, 1, p_x1);

    // GAT layer 1
    gemm_h<128, false><<<GB, 256>>>(p_x1, HID, HID, NN, W1, nullptr, nullptr, p_h, HID, 0);
    attn_scores<<<node_wblocks, T>>>(as1, ad1);
    gat_pull<<<node_wblocks, T>>>(nullptr, 0, p_agg);

    // outputs
    final_node<<<node_wblocks, T>>>(b1, Wa, ba, Wd, bd, out);
    pred_kernel<<<(NE + T - 1) / T, T>>>(edges, pred);
}